// round 1
// baseline (speedup 1.0000x reference)
#include <cuda_runtime.h>
#include <cuda_bf16.h>
#include <mma.h>

using namespace nvcuda;

// Problem constants
#define BB 4
#define SS 2048
#define DD 1024
// BETA = 1/sqrt(1024) = 1/32 exactly
#define BETA_F 0.03125f

// Scratch (allocation-free rule: __device__ globals)
__device__ float g_q[(long)BB * SS * DD];
__device__ float g_k[(long)BB * SS * DD];
__device__ float g_v[(long)BB * SS * DD];
__device__ float g_s[(long)BB * SS * SS];

// ---------------------------------------------------------------------------
// tf32 WMMA GEMM: C[M,N] = A[M,K] * op(B) (+ bias)
//   TRANS_B=false: B stored [K,N] row-major
//   TRANS_B=true : B stored [N,K] row-major (we compute A * B^T)
// Block tile 128x128, K-chunk 32, 256 threads (8 warps, 4x2 warp grid,
// each warp 32x64 via 2x4 m16n16k8 fragments). M,N,K multiples of 128/32.
// ---------------------------------------------------------------------------
template<bool TRANS_B, bool HAS_BIAS>
__global__ __launch_bounds__(256, 1)
void gemm_tf32(const float* __restrict__ A, const float* __restrict__ Bm,
               float* __restrict__ C, const float* __restrict__ bias,
               int M, int N, int K, long sA, long sB, long sC)
{
    __shared__ float As[128][36];      // 128 rows x 32 k (pad 36)
    __shared__ float Bs[32][132];      // 32 k x 128 n (pad 132)
    __shared__ float Cstage[8][16 * 20];

    const int tid  = threadIdx.x;
    const int warp = tid >> 5;
    const int lane = tid & 31;
    const int wm   = warp & 3;         // 0..3 -> m offset wm*32
    const int wn   = warp >> 2;        // 0..1 -> n offset wn*64
    const int rowBase = blockIdx.y * 128;
    const int colBase = blockIdx.x * 128;

    A  += (long)blockIdx.z * sA;
    Bm += (long)blockIdx.z * sB;
    C  += (long)blockIdx.z * sC;

    wmma::fragment<wmma::accumulator, 16, 16, 8, float> acc[2][4];
    #pragma unroll
    for (int mi = 0; mi < 2; mi++)
        #pragma unroll
        for (int ni = 0; ni < 4; ni++)
            wmma::fill_fragment(acc[mi][ni], 0.0f);

    for (int k0 = 0; k0 < K; k0 += 32) {
        // --- Load A tile (128x32), coalesced float4 ---
        #pragma unroll
        for (int i = 0; i < 4; i++) {
            int idx = tid + 256 * i;          // 0..1023 float4s
            int r   = idx >> 3;               // 8 float4 per row
            int c4  = idx & 7;
            float4 t = *(const float4*)(A + (long)(rowBase + r) * K + k0 + c4 * 4);
            *(float4*)(&As[r][c4 * 4]) = t;
        }
        // --- Load B tile (32x128) ---
        if (!TRANS_B) {
            #pragma unroll
            for (int i = 0; i < 4; i++) {
                int idx = tid + 256 * i;
                int r   = idx >> 5;           // 32 float4 per row
                int c4  = idx & 31;
                float4 t = *(const float4*)(Bm + (long)(k0 + r) * N + colBase + c4 * 4);
                *(float4*)(&Bs[r][c4 * 4]) = t;
            }
        } else {
            // B^T: read Bt[N,K] rows along K (coalesced), transpose into Bs[k][n]
            #pragma unroll
            for (int i = 0; i < 4; i++) {
                int idx = tid + 256 * i;
                int j   = idx >> 3;           // n index 0..127
                int d4  = idx & 7;            // k float4 index 0..7
                float4 t = *(const float4*)(Bm + (long)(colBase + j) * K + k0 + d4 * 4);
                Bs[d4 * 4 + 0][j] = t.x;
                Bs[d4 * 4 + 1][j] = t.y;
                Bs[d4 * 4 + 2][j] = t.z;
                Bs[d4 * 4 + 3][j] = t.w;
            }
        }
        __syncthreads();

        // --- Compute: 4 k-steps of 8 ---
        #pragma unroll
        for (int kk = 0; kk < 4; kk++) {
            wmma::fragment<wmma::matrix_a, 16, 16, 8, wmma::precision::tf32, wmma::row_major> af[2];
            wmma::fragment<wmma::matrix_b, 16, 16, 8, wmma::precision::tf32, wmma::row_major> bf[4];
            #pragma unroll
            for (int mi = 0; mi < 2; mi++) {
                wmma::load_matrix_sync(af[mi], &As[wm * 32 + mi * 16][kk * 8], 36);
                #pragma unroll
                for (int t = 0; t < af[mi].num_elements; t++)
                    af[mi].x[t] = wmma::__float_to_tf32(af[mi].x[t]);
            }
            #pragma unroll
            for (int ni = 0; ni < 4; ni++) {
                wmma::load_matrix_sync(bf[ni], &Bs[kk * 8][wn * 64 + ni * 16], 132);
                #pragma unroll
                for (int t = 0; t < bf[ni].num_elements; t++)
                    bf[ni].x[t] = wmma::__float_to_tf32(bf[ni].x[t]);
            }
            #pragma unroll
            for (int mi = 0; mi < 2; mi++)
                #pragma unroll
                for (int ni = 0; ni < 4; ni++)
                    wmma::mma_sync(acc[mi][ni], af[mi], bf[ni], acc[mi][ni]);
        }
        __syncthreads();
    }

    // --- Epilogue ---
    #pragma unroll
    for (int mi = 0; mi < 2; mi++) {
        #pragma unroll
        for (int ni = 0; ni < 4; ni++) {
            long cb = (long)(rowBase + wm * 32 + mi * 16) * N + colBase + wn * 64 + ni * 16;
            if (HAS_BIAS) {
                wmma::store_matrix_sync(&Cstage[warp][0], acc[mi][ni], 20, wmma::mem_row_major);
                __syncwarp();
                const float* bp = bias + colBase + wn * 64 + ni * 16;
                #pragma unroll
                for (int e = 0; e < 8; e++) {
                    int idx = lane + 32 * e;   // 0..255 over 16x16
                    int r = idx >> 4, c = idx & 15;
                    C[cb + (long)r * N + c] = Cstage[warp][r * 20 + c] + bp[c];
                }
                __syncwarp();
            } else {
                wmma::store_matrix_sync(C + cb, acc[mi][ni], N, wmma::mem_row_major);
            }
        }
    }
}

// ---------------------------------------------------------------------------
// Row softmax of beta*x, in place. One block per row of 2048 floats.
// ---------------------------------------------------------------------------
__global__ __launch_bounds__(256, 4)
void softmax_kernel(float* __restrict__ s, float beta)
{
    float* p = s + (long)blockIdx.x * SS;
    const int tid = threadIdx.x;

    float4 a = ((float4*)p)[tid];
    float4 b = ((float4*)p)[tid + 256];

    __shared__ float red[8];
    __shared__ float bc;

    // --- max ---
    float m = fmaxf(fmaxf(fmaxf(a.x, a.y), fmaxf(a.z, a.w)),
                    fmaxf(fmaxf(b.x, b.y), fmaxf(b.z, b.w)));
    #pragma unroll
    for (int o = 16; o; o >>= 1) m = fmaxf(m, __shfl_xor_sync(0xffffffffu, m, o));
    if ((tid & 31) == 0) red[tid >> 5] = m;
    __syncthreads();
    if (tid < 32) {
        float t = (tid < 8) ? red[tid] : -3.4e38f;
        #pragma unroll
        for (int o = 4; o; o >>= 1) t = fmaxf(t, __shfl_xor_sync(0xffffffffu, t, o));
        if (tid == 0) bc = t;
    }
    __syncthreads();
    m = bc;
    __syncthreads();   // protect red/bc reuse

    // --- exp + sum ---
    a.x = __expf(beta * (a.x - m)); a.y = __expf(beta * (a.y - m));
    a.z = __expf(beta * (a.z - m)); a.w = __expf(beta * (a.w - m));
    b.x = __expf(beta * (b.x - m)); b.y = __expf(beta * (b.y - m));
    b.z = __expf(beta * (b.z - m)); b.w = __expf(beta * (b.w - m));
    float sum = (a.x + a.y) + (a.z + a.w) + (b.x + b.y) + (b.z + b.w);
    #pragma unroll
    for (int o = 16; o; o >>= 1) sum += __shfl_xor_sync(0xffffffffu, sum, o);
    if ((tid & 31) == 0) red[tid >> 5] = sum;
    __syncthreads();
    if (tid < 32) {
        float t = (tid < 8) ? red[tid] : 0.0f;
        #pragma unroll
        for (int o = 4; o; o >>= 1) t += __shfl_xor_sync(0xffffffffu, t, o);
        if (tid == 0) bc = t;
    }
    __syncthreads();
    float inv = 1.0f / bc;

    a.x *= inv; a.y *= inv; a.z *= inv; a.w *= inv;
    b.x *= inv; b.y *= inv; b.z *= inv; b.w *= inv;
    ((float4*)p)[tid] = a;
    ((float4*)p)[tid + 256] = b;
}

// ---------------------------------------------------------------------------
extern "C" void kernel_launch(void* const* d_in, const int* in_sizes, int n_in,
                              void* d_out, int out_size)
{
    const float* query = (const float*)d_in[0];
    const float* key   = (const float*)d_in[1];
    const float* value = (const float*)d_in[2];
    const float* Wq    = (const float*)d_in[3];
    const float* bq    = (const float*)d_in[4];
    const float* Wk    = (const float*)d_in[5];
    const float* bk    = (const float*)d_in[6];
    const float* Wv    = (const float*)d_in[7];
    const float* bv    = (const float*)d_in[8];
    float* out = (float*)d_out;

    float *q, *k, *v, *s;
    cudaGetSymbolAddress((void**)&q, g_q);
    cudaGetSymbolAddress((void**)&k, g_k);
    cudaGetSymbolAddress((void**)&v, g_v);
    cudaGetSymbolAddress((void**)&s, g_s);

    dim3 thr(256);

    // Projections: [8192,1024] = [8192,1024] x [1024,1024] + bias
    dim3 gProj(DD / 128, (BB * SS) / 128, 1);
    gemm_tf32<false, true><<<gProj, thr>>>(query, Wq, q, bq, BB * SS, DD, DD, 0, 0, 0);
    gemm_tf32<false, true><<<gProj, thr>>>(key,   Wk, k, bk, BB * SS, DD, DD, 0, 0, 0);
    gemm_tf32<false, true><<<gProj, thr>>>(value, Wv, v, bv, BB * SS, DD, DD, 0, 0, 0);

    // Scores: per batch S[2048,2048] = q x k^T
    dim3 gScores(SS / 128, SS / 128, BB);
    gemm_tf32<true, false><<<gScores, thr>>>(q, k, s, nullptr, SS, SS, DD,
                                             (long)SS * DD, (long)SS * DD, (long)SS * SS);

    // Softmax(beta * scores) row-wise, in place
    softmax_kernel<<<BB * SS, 256>>>(s, BETA_F);

    // Out: per batch O[2048,1024] = A x v
    dim3 gOut(DD / 128, SS / 128, BB);
    gemm_tf32<false, false><<<gOut, thr>>>(s, v, out, nullptr, SS, DD, SS,
                                           (long)SS * SS, (long)SS * DD, (long)SS * DD);
}

// round 4
// speedup vs baseline: 3.9871x; 3.9871x over previous
#include <cuda_runtime.h>
#include <cuda_fp16.h>
#include <cstdint>

#define BB 4
#define SS 2048
#define DD 1024
#define BETA_F 0.03125f

// ---------------- scratch (__device__ globals, allocation-free) ----------------
__device__ __half g_xh[3][(long)BB * SS * DD];  // fp16 query/key/value
__device__ __half g_wT[3][(long)DD * DD];       // fp16 W^T  [n][k]
__device__ __half g_q [(long)BB * SS * DD];
__device__ __half g_k [(long)BB * SS * DD];
__device__ __half g_v [(long)BB * SS * DD];
__device__ __half g_vT[(long)BB * SS * DD];     // [d][s] per batch
__device__ float  g_s [(long)BB * SS * SS];     // f32 scores
__device__ __half g_a [(long)BB * SS * SS];     // fp16 softmax output

union H2U { __half2 h; unsigned u; };

// ---------------- asm helpers ----------------
__device__ __forceinline__ uint32_t smem_u32(const void* p) {
    uint32_t a;
    asm("{ .reg .u64 t; cvta.to.shared.u64 t, %1; cvt.u32.u64 %0, t; }" : "=r"(a) : "l"(p));
    return a;
}
#define CP16(dst, src) \
    asm volatile("cp.async.cg.shared.global [%0], [%1], 16;" :: "r"(dst), "l"(src) : "memory")
#define CPCOMMIT() asm volatile("cp.async.commit_group;" ::: "memory")
#define CPWAIT2()  asm volatile("cp.async.wait_group 2;" ::: "memory")
#define LDSM4(r0, r1, r2, r3, addr) \
    asm volatile("ldmatrix.sync.aligned.m8n8.x4.shared.b16 {%0,%1,%2,%3}, [%4];" \
        : "=r"(r0), "=r"(r1), "=r"(r2), "=r"(r3) : "r"(addr))
#define MMA16816(c, a, b) \
    asm volatile("mma.sync.aligned.m16n8k16.row.col.f32.f16.f16.f32 " \
        "{%0,%1,%2,%3}, {%4,%5,%6,%7}, {%8,%9}, {%0,%1,%2,%3};" \
        : "+f"((c)[0]), "+f"((c)[1]), "+f"((c)[2]), "+f"((c)[3]) \
        : "r"((a)[0]), "r"((a)[1]), "r"((a)[2]), "r"((a)[3]), "r"((b)[0]), "r"((b)[1]))

// ---------------- GEMM config ----------------
// C[M,N] = A[M,K] * B^T (+bias), A [M,K] and B [N,K] row-major fp16, BK=32.
// CTA 128x128, 256 threads, 8 warps as 2(m)x4(n), warp tile 64x32.
// smem rows padded to 40 halves (80B): ldmatrix chunk bank (5r+c)%8 distinct.
constexpr int ROWB   = 80;            // bytes per padded 32-half row
constexpr int TILEB  = 128 * ROWB;    // 10240
constexpr int STAGEB = 2 * TILEB;     // A + B
constexpr int STAGES = 4;
constexpr int SMEMB  = STAGES * STAGEB;  // 81920

template<int MODE>   // 0: f32 out, no bias   1: fp16 out, +bias
__global__ __launch_bounds__(256)
void gemm_h(const __half* __restrict__ A, const __half* __restrict__ Bm,
            void* __restrict__ Cv, const float* __restrict__ bias,
            int M, int N, int K, long sA, long sB, long sC)
{
    extern __shared__ char smem[];
    const int tid = threadIdx.x, lane = tid & 31, warp = tid >> 5;
    const int wm = warp & 1, wn = warp >> 1;     // warp tile 64(m) x 32(n)
    const int rowBase = blockIdx.y * 128, colBase = blockIdx.x * 128;

    A  += (long)blockIdx.z * sA + (long)rowBase * K;
    Bm += (long)blockIdx.z * sB + (long)colBase * K;

    const uint32_t sbase = smem_u32(smem);

    // cp.async: 2 threads per row; each thread 2x16B chunks for A, same for B
    const int ldr = tid >> 1;
    const int ldc = (tid & 1) * 2;   // chunk 0..3 base

    float acc[4][4][4];
    #pragma unroll
    for (int mf = 0; mf < 4; mf++)
        #pragma unroll
        for (int nf = 0; nf < 4; nf++)
            #pragma unroll
            for (int e = 0; e < 4; e++) acc[mf][nf][e] = 0.0f;

    const int nk = K >> 5;   // BK = 32 halves

    // ldmatrix per-lane address pieces
    const int arow = (lane & 7) + ((lane >> 3) & 1) * 8;
    const int kadd = (lane >> 4) * 8;

    // ---- prefetch STAGES-1 stages ----
    #pragma unroll
    for (int s = 0; s < STAGES - 1; s++) {
        const __half* ag = A  + (long)ldr * K + s * 32 + ldc * 8;
        const __half* bg = Bm + (long)ldr * K + s * 32 + ldc * 8;
        uint32_t ad = sbase + s * STAGEB + ldr * ROWB + ldc * 16;
        CP16(ad, ag);            CP16(ad + 16, ag + 8);
        CP16(ad + TILEB, bg);    CP16(ad + TILEB + 16, bg + 8);
        CPCOMMIT();
    }

    for (int ck = 0; ck < nk; ck++) {
        CPWAIT2();
        __syncthreads();

        // issue next stage
        const int nxt = ck + STAGES - 1;
        if (nxt < nk) {
            const int nb = nxt & (STAGES - 1);
            const __half* ag = A  + (long)ldr * K + nxt * 32 + ldc * 8;
            const __half* bg = Bm + (long)ldr * K + nxt * 32 + ldc * 8;
            uint32_t ad = sbase + nb * STAGEB + ldr * ROWB + ldc * 16;
            CP16(ad, ag);            CP16(ad + 16, ag + 8);
            CP16(ad + TILEB, bg);    CP16(ad + TILEB + 16, bg + 8);
        }
        CPCOMMIT();

        // compute this stage: 2 k16-steps
        const int buf = ck & (STAGES - 1);
        const uint32_t abase = sbase + buf * STAGEB;
        const uint32_t bbase = abase + TILEB;
        #pragma unroll
        for (int ks = 0; ks < 2; ks++) {
            uint32_t a[4][4], b[4][2];
            #pragma unroll
            for (int mf = 0; mf < 4; mf++) {
                uint32_t addr = abase + (wm * 64 + mf * 16 + arow) * ROWB + (ks * 16 + kadd) * 2;
                LDSM4(a[mf][0], a[mf][1], a[mf][2], a[mf][3], addr);
            }
            #pragma unroll
            for (int p = 0; p < 2; p++) {
                uint32_t t0, t1, t2, t3;
                uint32_t addr = bbase + (wn * 32 + p * 16 + arow) * ROWB + (ks * 16 + kadd) * 2;
                LDSM4(t0, t1, t2, t3, addr);
                b[p * 2][0] = t0; b[p * 2][1] = t2;
                b[p * 2 + 1][0] = t1; b[p * 2 + 1][1] = t3;
            }
            #pragma unroll
            for (int mf = 0; mf < 4; mf++)
                #pragma unroll
                for (int nf = 0; nf < 4; nf++)
                    MMA16816(acc[mf][nf], a[mf], b[nf]);
        }
    }

    // ---- epilogue ----
    const int r0 = lane >> 2;
    const int c0 = (lane & 3) * 2;
    #pragma unroll
    for (int mf = 0; mf < 4; mf++) {
        #pragma unroll
        for (int nf = 0; nf < 4; nf++) {
            int gr = rowBase + wm * 64 + mf * 16 + r0;
            int gc = colBase + wn * 32 + nf * 8 + c0;
            float* ac = acc[mf][nf];
            if (MODE == 0) {
                float* C = (float*)Cv + (long)blockIdx.z * sC;
                *(float2*)(C + (long)gr * N + gc)       = make_float2(ac[0], ac[1]);
                *(float2*)(C + (long)(gr + 8) * N + gc) = make_float2(ac[2], ac[3]);
            } else {
                __half* C = (__half*)Cv + (long)blockIdx.z * sC;
                float b0 = __ldg(bias + gc), b1 = __ldg(bias + gc + 1);
                H2U u0, u1;
                u0.h = __floats2half2_rn(ac[0] + b0, ac[1] + b1);
                u1.h = __floats2half2_rn(ac[2] + b0, ac[3] + b1);
                *(unsigned*)(C + (long)gr * N + gc)       = u0.u;
                *(unsigned*)(C + (long)(gr + 8) * N + gc) = u1.u;
            }
        }
    }
}

// ---------------- f32 -> f16 convert (8 elems/thread) ----------------
__global__ __launch_bounds__(256)
void f2h_kernel(const float* __restrict__ in, __half* __restrict__ out)
{
    long i = ((long)blockIdx.x * 256 + threadIdx.x) * 8;
    float4 a = *(const float4*)(in + i);
    float4 b = *(const float4*)(in + i + 4);
    H2U h0, h1, h2, h3;
    h0.h = __floats2half2_rn(a.x, a.y); h1.h = __floats2half2_rn(a.z, a.w);
    h2.h = __floats2half2_rn(b.x, b.y); h3.h = __floats2half2_rn(b.z, b.w);
    *(uint4*)(out + i) = make_uint4(h0.u, h1.u, h2.u, h3.u);
}

// ---------------- transpose f32 [R][C] -> f16 [C][R] ----------------
__global__ __launch_bounds__(256)
void transWh_kernel(const float* __restrict__ in, __half* __restrict__ out, int R, int C)
{
    __shared__ float t[32][33];
    int tx = threadIdx.x, ty = threadIdx.y;
    int x = blockIdx.x * 32 + tx, y0 = blockIdx.y * 32 + ty;
    #pragma unroll
    for (int j = 0; j < 32; j += 8) t[ty + j][tx] = in[(long)(y0 + j) * C + x];
    __syncthreads();
    int ox = blockIdx.y * 32 + tx, oy0 = blockIdx.x * 32 + ty;
    #pragma unroll
    for (int j = 0; j < 32; j += 8)
        out[(long)(oy0 + j) * R + ox] = __float2half(t[tx][ty + j]);
}

// ---------------- transpose f16 [R][C] -> f16 [C][R], batched ----------------
__global__ __launch_bounds__(256)
void transH_kernel(const __half* __restrict__ in, __half* __restrict__ out,
                   int R, int C, long sIn, long sOut)
{
    __shared__ __half t[32][33];
    in  += (long)blockIdx.z * sIn;
    out += (long)blockIdx.z * sOut;
    int tx = threadIdx.x, ty = threadIdx.y;
    int x = blockIdx.x * 32 + tx, y0 = blockIdx.y * 32 + ty;
    #pragma unroll
    for (int j = 0; j < 32; j += 8) t[ty + j][tx] = in[(long)(y0 + j) * C + x];
    __syncthreads();
    int ox = blockIdx.y * 32 + tx, oy0 = blockIdx.x * 32 + ty;
    #pragma unroll
    for (int j = 0; j < 32; j += 8)
        out[(long)(oy0 + j) * R + ox] = t[tx][ty + j];
}

// ---------------- softmax(beta*x) f32 in -> f16 out ----------------
__global__ __launch_bounds__(256, 4)
void softmax_kernel(const float* __restrict__ s, __half* __restrict__ ah, float beta)
{
    const float* p = s + (long)blockIdx.x * SS;
    __half* po = ah + (long)blockIdx.x * SS;
    const int tid = threadIdx.x;

    float4 a = ((const float4*)p)[tid];
    float4 b = ((const float4*)p)[tid + 256];

    __shared__ float red[8];
    __shared__ float bc;

    float m = fmaxf(fmaxf(fmaxf(a.x, a.y), fmaxf(a.z, a.w)),
                    fmaxf(fmaxf(b.x, b.y), fmaxf(b.z, b.w)));
    #pragma unroll
    for (int o = 16; o; o >>= 1) m = fmaxf(m, __shfl_xor_sync(0xffffffffu, m, o));
    if ((tid & 31) == 0) red[tid >> 5] = m;
    __syncthreads();
    if (tid < 32) {
        float t = (tid < 8) ? red[tid] : -3.4e38f;
        #pragma unroll
        for (int o = 4; o; o >>= 1) t = fmaxf(t, __shfl_xor_sync(0xffffffffu, t, o));
        if (tid == 0) bc = t;
    }
    __syncthreads();
    m = bc;
    __syncthreads();

    a.x = __expf(beta * (a.x - m)); a.y = __expf(beta * (a.y - m));
    a.z = __expf(beta * (a.z - m)); a.w = __expf(beta * (a.w - m));
    b.x = __expf(beta * (b.x - m)); b.y = __expf(beta * (b.y - m));
    b.z = __expf(beta * (b.z - m)); b.w = __expf(beta * (b.w - m));
    float sum = (a.x + a.y) + (a.z + a.w) + (b.x + b.y) + (b.z + b.w);
    #pragma unroll
    for (int o = 16; o; o >>= 1) sum += __shfl_xor_sync(0xffffffffu, sum, o);
    if ((tid & 31) == 0) red[tid >> 5] = sum;
    __syncthreads();
    if (tid < 32) {
        float t = (tid < 8) ? red[tid] : 0.0f;
        #pragma unroll
        for (int o = 4; o; o >>= 1) t += __shfl_xor_sync(0xffffffffu, t, o);
        if (tid == 0) bc = t;
    }
    __syncthreads();
    float inv = 1.0f / bc;

    H2U u0, u1, u2, u3;
    u0.h = __floats2half2_rn(a.x * inv, a.y * inv);
    u1.h = __floats2half2_rn(a.z * inv, a.w * inv);
    u2.h = __floats2half2_rn(b.x * inv, b.y * inv);
    u3.h = __floats2half2_rn(b.z * inv, b.w * inv);
    ((uint2*)po)[tid]       = make_uint2(u0.u, u1.u);
    ((uint2*)po)[tid + 256] = make_uint2(u2.u, u3.u);
}

// ---------------------------------------------------------------------------
extern "C" void kernel_launch(void* const* d_in, const int* in_sizes, int n_in,
                              void* d_out, int out_size)
{
    const float* query = (const float*)d_in[0];
    const float* key   = (const float*)d_in[1];
    const float* value = (const float*)d_in[2];
    const float* Wq    = (const float*)d_in[3];
    const float* bq    = (const float*)d_in[4];
    const float* Wk    = (const float*)d_in[5];
    const float* bk    = (const float*)d_in[6];
    const float* Wv    = (const float*)d_in[7];
    const float* bv    = (const float*)d_in[8];
    float* out = (float*)d_out;

    __half *xh, *wT, *q, *k, *v, *vT, *ah;
    float *s;
    cudaGetSymbolAddress((void**)&xh, g_xh);
    cudaGetSymbolAddress((void**)&wT, g_wT);
    cudaGetSymbolAddress((void**)&q,  g_q);
    cudaGetSymbolAddress((void**)&k,  g_k);
    cudaGetSymbolAddress((void**)&v,  g_v);
    cudaGetSymbolAddress((void**)&vT, g_vT);
    cudaGetSymbolAddress((void**)&s,  g_s);
    cudaGetSymbolAddress((void**)&ah, g_a);

    static bool attr_set = false;
    if (!attr_set) {
        cudaFuncSetAttribute(gemm_h<0>, cudaFuncAttributeMaxDynamicSharedMemorySize, SMEMB);
        cudaFuncSetAttribute(gemm_h<1>, cudaFuncAttributeMaxDynamicSharedMemorySize, SMEMB);
        attr_set = true;
    }

    const long NX = (long)BB * SS * DD;   // 8M elems
    const long ND = (long)DD * DD;

    // 1) convert inputs to fp16
    f2h_kernel<<<(int)(NX / 2048), 256>>>(query, xh + 0 * NX);
    f2h_kernel<<<(int)(NX / 2048), 256>>>(key,   xh + 1 * NX);
    f2h_kernel<<<(int)(NX / 2048), 256>>>(value, xh + 2 * NX);

    // 2) transpose + convert weights -> [n][k] fp16
    dim3 tT(32, 8);
    dim3 gW(DD / 32, DD / 32);
    transWh_kernel<<<gW, tT>>>(Wq, wT + 0 * ND, DD, DD);
    transWh_kernel<<<gW, tT>>>(Wk, wT + 1 * ND, DD, DD);
    transWh_kernel<<<gW, tT>>>(Wv, wT + 2 * ND, DD, DD);

    // 3) projections: fp16 out + bias
    dim3 gProj(DD / 128, (BB * SS) / 128, 1);
    gemm_h<1><<<gProj, 256, SMEMB>>>(xh + 0 * NX, wT + 0 * ND, q, bq, BB * SS, DD, DD, 0, 0, 0);
    gemm_h<1><<<gProj, 256, SMEMB>>>(xh + 1 * NX, wT + 1 * ND, k, bk, BB * SS, DD, DD, 0, 0, 0);
    gemm_h<1><<<gProj, 256, SMEMB>>>(xh + 2 * NX, wT + 2 * ND, v, bv, BB * SS, DD, DD, 0, 0, 0);

    // 4) transpose v per batch -> vT [d][s]
    dim3 gVT(DD / 32, SS / 32, BB);
    transH_kernel<<<gVT, tT>>>(v, vT, SS, DD, (long)SS * DD, (long)SS * DD);

    // 5) scores: S = q k^T (f32 out)
    dim3 gScores(SS / 128, SS / 128, BB);
    gemm_h<0><<<gScores, 256, SMEMB>>>(q, k, s, nullptr, SS, SS, DD,
                                       (long)SS * DD, (long)SS * DD, (long)SS * SS);

    // 6) softmax(beta*S) -> fp16 A
    softmax_kernel<<<BB * SS, 256>>>(s, ah, BETA_F);

    // 7) out = A vT^T (f32 out to d_out)
    dim3 gOut(DD / 128, SS / 128, BB);
    gemm_h<0><<<gOut, 256, SMEMB>>>(ah, vT, out, nullptr, SS, DD, SS,
                                    (long)SS * SS, (long)SS * DD, (long)SS * DD);
}

// round 5
// speedup vs baseline: 4.1752x; 1.0472x over previous
#include <cuda_runtime.h>
#include <cuda_fp16.h>
#include <cstdint>

#define BB 4
#define SS 2048
#define DD 1024
#define BETA_F 0.03125f

// ---------------- scratch (__device__ globals, allocation-free) ----------------
__device__ __half g_xh[3][(long)BB * SS * DD];  // fp16 query/key/value
__device__ __half g_wT[3][(long)DD * DD];       // fp16 W^T  [n][k]
__device__ __half g_q [(long)BB * SS * DD];
__device__ __half g_k [(long)BB * SS * DD];
__device__ __half g_v [(long)BB * SS * DD];
__device__ __half g_vT[(long)BB * SS * DD];     // [d][s] per batch
__device__ float  g_s [(long)BB * SS * SS];     // f32 scores
__device__ __half g_a [(long)BB * SS * SS];     // fp16 softmax output

union H2U { __half2 h; unsigned u; };

// ---------------- asm helpers ----------------
__device__ __forceinline__ uint32_t smem_u32(const void* p) {
    uint32_t a;
    asm("{ .reg .u64 t; cvta.to.shared.u64 t, %1; cvt.u32.u64 %0, t; }" : "=r"(a) : "l"(p));
    return a;
}
#define CP16(dst, src) \
    asm volatile("cp.async.cg.shared.global [%0], [%1], 16;" :: "r"(dst), "l"(src) : "memory")
#define CPCOMMIT() asm volatile("cp.async.commit_group;" ::: "memory")
#define CPWAIT2()  asm volatile("cp.async.wait_group 2;" ::: "memory")
#define LDSM4(r0, r1, r2, r3, addr) \
    asm volatile("ldmatrix.sync.aligned.m8n8.x4.shared.b16 {%0,%1,%2,%3}, [%4];" \
        : "=r"(r0), "=r"(r1), "=r"(r2), "=r"(r3) : "r"(addr))
#define MMA16816(c, a, b) \
    asm volatile("mma.sync.aligned.m16n8k16.row.col.f32.f16.f16.f32 " \
        "{%0,%1,%2,%3}, {%4,%5,%6,%7}, {%8,%9}, {%0,%1,%2,%3};" \
        : "+f"((c)[0]), "+f"((c)[1]), "+f"((c)[2]), "+f"((c)[3]) \
        : "r"((a)[0]), "r"((a)[1]), "r"((a)[2]), "r"((a)[3]), "r"((b)[0]), "r"((b)[1]))

// ---------------- GEMM config ----------------
// C[M,N] = A[M,K] * B^T (+bias), A [M,K] and B [N,K] row-major fp16, BK=32.
// CTA 128x128, 256 threads, 8 warps as 2(m)x4(n), warp tile 64x32.
// smem rows padded to 40 halves (80B): ldmatrix chunk bank (5r+c)%8 distinct.
// __launch_bounds__(256, 2): cap regs at 128 -> 2 CTAs/SM (160KB smem of 228KB),
// 16 resident warps hide cp.async waits, syncthreads and epilogue bubbles.
constexpr int ROWB   = 80;            // bytes per padded 32-half row
constexpr int TILEB  = 128 * ROWB;    // 10240
constexpr int STAGEB = 2 * TILEB;     // A + B
constexpr int STAGES = 4;
constexpr int SMEMB  = STAGES * STAGEB;  // 81920

template<int MODE>   // 0: f32 out, no bias   1: fp16 out, +bias
__global__ __launch_bounds__(256, 2)
void gemm_h(const __half* __restrict__ A, const __half* __restrict__ Bm,
            void* __restrict__ Cv, const float* __restrict__ bias,
            int M, int N, int K, long sA, long sB, long sC)
{
    extern __shared__ char smem[];
    const int tid = threadIdx.x, lane = tid & 31, warp = tid >> 5;
    const int wm = warp & 1, wn = warp >> 1;     // warp tile 64(m) x 32(n)
    const int rowBase = blockIdx.y * 128, colBase = blockIdx.x * 128;

    A  += (long)blockIdx.z * sA + (long)rowBase * K;
    Bm += (long)blockIdx.z * sB + (long)colBase * K;

    const uint32_t sbase = smem_u32(smem);

    // cp.async: 2 threads per row; each thread 2x16B chunks for A, same for B
    const int ldr = tid >> 1;
    const int ldc = (tid & 1) * 2;   // chunk 0..3 base

    float acc[4][4][4];
    #pragma unroll
    for (int mf = 0; mf < 4; mf++)
        #pragma unroll
        for (int nf = 0; nf < 4; nf++)
            #pragma unroll
            for (int e = 0; e < 4; e++) acc[mf][nf][e] = 0.0f;

    const int nk = K >> 5;   // BK = 32 halves

    // ldmatrix per-lane address pieces
    const int arow = (lane & 7) + ((lane >> 3) & 1) * 8;
    const int kadd = (lane >> 4) * 8;

    // ---- prefetch STAGES-1 stages ----
    #pragma unroll
    for (int s = 0; s < STAGES - 1; s++) {
        const __half* ag = A  + (long)ldr * K + s * 32 + ldc * 8;
        const __half* bg = Bm + (long)ldr * K + s * 32 + ldc * 8;
        uint32_t ad = sbase + s * STAGEB + ldr * ROWB + ldc * 16;
        CP16(ad, ag);            CP16(ad + 16, ag + 8);
        CP16(ad + TILEB, bg);    CP16(ad + TILEB + 16, bg + 8);
        CPCOMMIT();
    }

    for (int ck = 0; ck < nk; ck++) {
        CPWAIT2();
        __syncthreads();

        // issue next stage
        const int nxt = ck + STAGES - 1;
        if (nxt < nk) {
            const int nb = nxt & (STAGES - 1);
            const __half* ag = A  + (long)ldr * K + nxt * 32 + ldc * 8;
            const __half* bg = Bm + (long)ldr * K + nxt * 32 + ldc * 8;
            uint32_t ad = sbase + nb * STAGEB + ldr * ROWB + ldc * 16;
            CP16(ad, ag);            CP16(ad + 16, ag + 8);
            CP16(ad + TILEB, bg);    CP16(ad + TILEB + 16, bg + 8);
        }
        CPCOMMIT();

        // compute this stage: 2 k16-steps
        const int buf = ck & (STAGES - 1);
        const uint32_t abase = sbase + buf * STAGEB;
        const uint32_t bbase = abase + TILEB;
        #pragma unroll
        for (int ks = 0; ks < 2; ks++) {
            uint32_t a[4][4], b[4][2];
            #pragma unroll
            for (int mf = 0; mf < 4; mf++) {
                uint32_t addr = abase + (wm * 64 + mf * 16 + arow) * ROWB + (ks * 16 + kadd) * 2;
                LDSM4(a[mf][0], a[mf][1], a[mf][2], a[mf][3], addr);
            }
            #pragma unroll
            for (int p = 0; p < 2; p++) {
                uint32_t t0, t1, t2, t3;
                uint32_t addr = bbase + (wn * 32 + p * 16 + arow) * ROWB + (ks * 16 + kadd) * 2;
                LDSM4(t0, t1, t2, t3, addr);
                b[p * 2][0] = t0; b[p * 2][1] = t2;
                b[p * 2 + 1][0] = t1; b[p * 2 + 1][1] = t3;
            }
            #pragma unroll
            for (int mf = 0; mf < 4; mf++)
                #pragma unroll
                for (int nf = 0; nf < 4; nf++)
                    MMA16816(acc[mf][nf], a[mf], b[nf]);
        }
    }

    // ---- epilogue ----
    const int r0 = lane >> 2;
    const int c0 = (lane & 3) * 2;
    #pragma unroll
    for (int mf = 0; mf < 4; mf++) {
        #pragma unroll
        for (int nf = 0; nf < 4; nf++) {
            int gr = rowBase + wm * 64 + mf * 16 + r0;
            int gc = colBase + wn * 32 + nf * 8 + c0;
            float* ac = acc[mf][nf];
            if (MODE == 0) {
                float* C = (float*)Cv + (long)blockIdx.z * sC;
                *(float2*)(C + (long)gr * N + gc)       = make_float2(ac[0], ac[1]);
                *(float2*)(C + (long)(gr + 8) * N + gc) = make_float2(ac[2], ac[3]);
            } else {
                __half* C = (__half*)Cv + (long)blockIdx.z * sC;
                float b0 = __ldg(bias + gc), b1 = __ldg(bias + gc + 1);
                H2U u0, u1;
                u0.h = __floats2half2_rn(ac[0] + b0, ac[1] + b1);
                u1.h = __floats2half2_rn(ac[2] + b0, ac[3] + b1);
                *(unsigned*)(C + (long)gr * N + gc)       = u0.u;
                *(unsigned*)(C + (long)(gr + 8) * N + gc) = u1.u;
            }
        }
    }
}

// ---------------- f32 -> f16 convert (8 elems/thread) ----------------
__global__ __launch_bounds__(256)
void f2h_kernel(const float* __restrict__ in, __half* __restrict__ out)
{
    long i = ((long)blockIdx.x * 256 + threadIdx.x) * 8;
    float4 a = *(const float4*)(in + i);
    float4 b = *(const float4*)(in + i + 4);
    H2U h0, h1, h2, h3;
    h0.h = __floats2half2_rn(a.x, a.y); h1.h = __floats2half2_rn(a.z, a.w);
    h2.h = __floats2half2_rn(b.x, b.y); h3.h = __floats2half2_rn(b.z, b.w);
    *(uint4*)(out + i) = make_uint4(h0.u, h1.u, h2.u, h3.u);
}

// ---------------- transpose f32 [R][C] -> f16 [C][R] ----------------
__global__ __launch_bounds__(256)
void transWh_kernel(const float* __restrict__ in, __half* __restrict__ out, int R, int C)
{
    __shared__ float t[32][33];
    int tx = threadIdx.x, ty = threadIdx.y;
    int x = blockIdx.x * 32 + tx, y0 = blockIdx.y * 32 + ty;
    #pragma unroll
    for (int j = 0; j < 32; j += 8) t[ty + j][tx] = in[(long)(y0 + j) * C + x];
    __syncthreads();
    int ox = blockIdx.y * 32 + tx, oy0 = blockIdx.x * 32 + ty;
    #pragma unroll
    for (int j = 0; j < 32; j += 8)
        out[(long)(oy0 + j) * R + ox] = __float2half(t[tx][ty + j]);
}

// ---------------- transpose f16 [R][C] -> f16 [C][R], batched ----------------
__global__ __launch_bounds__(256)
void transH_kernel(const __half* __restrict__ in, __half* __restrict__ out,
                   int R, int C, long sIn, long sOut)
{
    __shared__ __half t[32][33];
    in  += (long)blockIdx.z * sIn;
    out += (long)blockIdx.z * sOut;
    int tx = threadIdx.x, ty = threadIdx.y;
    int x = blockIdx.x * 32 + tx, y0 = blockIdx.y * 32 + ty;
    #pragma unroll
    for (int j = 0; j < 32; j += 8) t[ty + j][tx] = in[(long)(y0 + j) * C + x];
    __syncthreads();
    int ox = blockIdx.y * 32 + tx, oy0 = blockIdx.x * 32 + ty;
    #pragma unroll
    for (int j = 0; j < 32; j += 8)
        out[(long)(oy0 + j) * R + ox] = t[tx][ty + j];
}

// ---------------- softmax(beta*x) f32 in -> f16 out ----------------
__global__ __launch_bounds__(256, 4)
void softmax_kernel(const float* __restrict__ s, __half* __restrict__ ah, float beta)
{
    const float* p = s + (long)blockIdx.x * SS;
    __half* po = ah + (long)blockIdx.x * SS;
    const int tid = threadIdx.x;

    float4 a = ((const float4*)p)[tid];
    float4 b = ((const float4*)p)[tid + 256];

    __shared__ float red[8];
    __shared__ float bc;

    float m = fmaxf(fmaxf(fmaxf(a.x, a.y), fmaxf(a.z, a.w)),
                    fmaxf(fmaxf(b.x, b.y), fmaxf(b.z, b.w)));
    #pragma unroll
    for (int o = 16; o; o >>= 1) m = fmaxf(m, __shfl_xor_sync(0xffffffffu, m, o));
    if ((tid & 31) == 0) red[tid >> 5] = m;
    __syncthreads();
    if (tid < 32) {
        float t = (tid < 8) ? red[tid] : -3.4e38f;
        #pragma unroll
        for (int o = 4; o; o >>= 1) t = fmaxf(t, __shfl_xor_sync(0xffffffffu, t, o));
        if (tid == 0) bc = t;
    }
    __syncthreads();
    m = bc;
    __syncthreads();

    a.x = __expf(beta * (a.x - m)); a.y = __expf(beta * (a.y - m));
    a.z = __expf(beta * (a.z - m)); a.w = __expf(beta * (a.w - m));
    b.x = __expf(beta * (b.x - m)); b.y = __expf(beta * (b.y - m));
    b.z = __expf(beta * (b.z - m)); b.w = __expf(beta * (b.w - m));
    float sum = (a.x + a.y) + (a.z + a.w) + (b.x + b.y) + (b.z + b.w);
    #pragma unroll
    for (int o = 16; o; o >>= 1) sum += __shfl_xor_sync(0xffffffffu, sum, o);
    if ((tid & 31) == 0) red[tid >> 5] = sum;
    __syncthreads();
    if (tid < 32) {
        float t = (tid < 8) ? red[tid] : 0.0f;
        #pragma unroll
        for (int o = 4; o; o >>= 1) t += __shfl_xor_sync(0xffffffffu, t, o);
        if (tid == 0) bc = t;
    }
    __syncthreads();
    float inv = 1.0f / bc;

    H2U u0, u1, u2, u3;
    u0.h = __floats2half2_rn(a.x * inv, a.y * inv);
    u1.h = __floats2half2_rn(a.z * inv, a.w * inv);
    u2.h = __floats2half2_rn(b.x * inv, b.y * inv);
    u3.h = __floats2half2_rn(b.z * inv, b.w * inv);
    ((uint2*)po)[tid]       = make_uint2(u0.u, u1.u);
    ((uint2*)po)[tid + 256] = make_uint2(u2.u, u3.u);
}

// ---------------------------------------------------------------------------
extern "C" void kernel_launch(void* const* d_in, const int* in_sizes, int n_in,
                              void* d_out, int out_size)
{
    const float* query = (const float*)d_in[0];
    const float* key   = (const float*)d_in[1];
    const float* value = (const float*)d_in[2];
    const float* Wq    = (const float*)d_in[3];
    const float* bq    = (const float*)d_in[4];
    const float* Wk    = (const float*)d_in[5];
    const float* bk    = (const float*)d_in[6];
    const float* Wv    = (const float*)d_in[7];
    const float* bv    = (const float*)d_in[8];
    float* out = (float*)d_out;

    __half *xh, *wT, *q, *k, *v, *vT, *ah;
    float *s;
    cudaGetSymbolAddress((void**)&xh, g_xh);
    cudaGetSymbolAddress((void**)&wT, g_wT);
    cudaGetSymbolAddress((void**)&q,  g_q);
    cudaGetSymbolAddress((void**)&k,  g_k);
    cudaGetSymbolAddress((void**)&v,  g_v);
    cudaGetSymbolAddress((void**)&vT, g_vT);
    cudaGetSymbolAddress((void**)&s,  g_s);
    cudaGetSymbolAddress((void**)&ah, g_a);

    static bool attr_set = false;
    if (!attr_set) {
        cudaFuncSetAttribute(gemm_h<0>, cudaFuncAttributeMaxDynamicSharedMemorySize, SMEMB);
        cudaFuncSetAttribute(gemm_h<1>, cudaFuncAttributeMaxDynamicSharedMemorySize, SMEMB);
        attr_set = true;
    }

    const long NX = (long)BB * SS * DD;   // 8M elems
    const long ND = (long)DD * DD;

    // 1) convert inputs to fp16
    f2h_kernel<<<(int)(NX / 2048), 256>>>(query, xh + 0 * NX);
    f2h_kernel<<<(int)(NX / 2048), 256>>>(key,   xh + 1 * NX);
    f2h_kernel<<<(int)(NX / 2048), 256>>>(value, xh + 2 * NX);

    // 2) transpose + convert weights -> [n][k] fp16
    dim3 tT(32, 8);
    dim3 gW(DD / 32, DD / 32);
    transWh_kernel<<<gW, tT>>>(Wq, wT + 0 * ND, DD, DD);
    transWh_kernel<<<gW, tT>>>(Wk, wT + 1 * ND, DD, DD);
    transWh_kernel<<<gW, tT>>>(Wv, wT + 2 * ND, DD, DD);

    // 3) projections: fp16 out + bias
    dim3 gProj(DD / 128, (BB * SS) / 128, 1);
    gemm_h<1><<<gProj, 256, SMEMB>>>(xh + 0 * NX, wT + 0 * ND, q, bq, BB * SS, DD, DD, 0, 0, 0);
    gemm_h<1><<<gProj, 256, SMEMB>>>(xh + 1 * NX, wT + 1 * ND, k, bk, BB * SS, DD, DD, 0, 0, 0);
    gemm_h<1><<<gProj, 256, SMEMB>>>(xh + 2 * NX, wT + 2 * ND, v, bv, BB * SS, DD, DD, 0, 0, 0);

    // 4) transpose v per batch -> vT [d][s]
    dim3 gVT(DD / 32, SS / 32, BB);
    transH_kernel<<<gVT, tT>>>(v, vT, SS, DD, (long)SS * DD, (long)SS * DD);

    // 5) scores: S = q k^T (f32 out)
    dim3 gScores(SS / 128, SS / 128, BB);
    gemm_h<0><<<gScores, 256, SMEMB>>>(q, k, s, nullptr, SS, SS, DD,
                                       (long)SS * DD, (long)SS * DD, (long)SS * SS);

    // 6) softmax(beta*S) -> fp16 A
    softmax_kernel<<<BB * SS, 256>>>(s, ah, BETA_F);

    // 7) out = A vT^T (f32 out to d_out)
    dim3 gOut(DD / 128, SS / 128, BB);
    gemm_h<0><<<gOut, 256, SMEMB>>>(ah, vT, out, nullptr, SS, DD, SS,
                                    (long)SS * SS, (long)SS * DD, (long)SS * DD);
}

// round 7
// speedup vs baseline: 4.3486x; 1.0415x over previous
#include <cuda_runtime.h>
#include <cuda_fp16.h>
#include <cstdint>

#define BB 4
#define SS 2048
#define DD 1024
#define BETA_F 0.03125f

// ---------------- scratch (__device__ globals, allocation-free) ----------------
__device__ __half g_xh[3][(long)BB * SS * DD];  // fp16 query/key/value
__device__ __half g_wT[3][(long)DD * DD];       // fp16 W^T  [n][k]
__device__ __half g_q [(long)BB * SS * DD];
__device__ __half g_k [(long)BB * SS * DD];
__device__ __half g_v [(long)BB * SS * DD];
__device__ __half g_vT[(long)BB * SS * DD];     // [d][s] per batch
__device__ float  g_s [(long)BB * SS * SS];     // f32 scores
__device__ __half g_a [(long)BB * SS * SS];     // fp16 softmax output

union H2U { __half2 h; unsigned u; };

// ---------------- asm helpers ----------------
__device__ __forceinline__ uint32_t smem_u32(const void* p) {
    uint32_t a;
    asm("{ .reg .u64 t; cvta.to.shared.u64 t, %1; cvt.u32.u64 %0, t; }" : "=r"(a) : "l"(p));
    return a;
}
#define CP16(dst, src) \
    asm volatile("cp.async.cg.shared.global [%0], [%1], 16;" :: "r"(dst), "l"(src) : "memory")
#define CPCOMMIT() asm volatile("cp.async.commit_group;" ::: "memory")
#define CPWAIT1()  asm volatile("cp.async.wait_group 1;" ::: "memory")
#define LDSM4(r0, r1, r2, r3, addr) \
    asm volatile("ldmatrix.sync.aligned.m8n8.x4.shared.b16 {%0,%1,%2,%3}, [%4];" \
        : "=r"(r0), "=r"(r1), "=r"(r2), "=r"(r3) : "r"(addr))
#define MMA16816(c, a, b) \
    asm volatile("mma.sync.aligned.m16n8k16.row.col.f32.f16.f16.f32 " \
        "{%0,%1,%2,%3}, {%4,%5,%6,%7}, {%8,%9}, {%0,%1,%2,%3};" \
        : "+f"((c)[0]), "+f"((c)[1]), "+f"((c)[2]), "+f"((c)[3]) \
        : "r"((a)[0]), "r"((a)[1]), "r"((a)[2]), "r"((a)[3]), "r"((b)[0]), "r"((b)[1]))

// ---------------- GEMM config ----------------
// C[M,N] = A[M,K] * B^T (+bias), A [M,K] and B [N,K] row-major fp16, BK=64.
// CTA 128x128, 256 threads, 8 warps as 2(m)x4(n), warp tile 64x32.
// smem rows padded to 72 halves (144B = 9 chunks): ldmatrix chunk bank
// (9r+c)%8 = (r+c)%8 distinct across 8 rows -> conflict-free.
// STAGES=3, 110.6KB smem -> 2 CTAs/SM (221KB of 228KB), regs capped 128.
constexpr int ROWB   = 144;           // bytes per padded 64-half row
constexpr int TILEB  = 128 * ROWB;    // 18432
constexpr int STAGEB = 2 * TILEB;     // A + B = 36864
constexpr int STAGES = 3;
constexpr int SMEMB  = STAGES * STAGEB;  // 110592

template<int MODE>   // 0: f32 out, no bias   1: fp16 out, +bias
__global__ __launch_bounds__(256, 2)
void gemm_h(const __half* __restrict__ A, const __half* __restrict__ Bm,
            void* __restrict__ Cv, const float* __restrict__ bias,
            int M, int N, int K, long sA, long sB, long sC)
{
    extern __shared__ char smem[];
    const int tid = threadIdx.x, lane = tid & 31, warp = tid >> 5;
    const int wm = warp & 1, wn = warp >> 1;     // warp tile 64(m) x 32(n)
    const int rowBase = blockIdx.y * 128, colBase = blockIdx.x * 128;

    A  += (long)blockIdx.z * sA + (long)rowBase * K;
    Bm += (long)blockIdx.z * sB + (long)colBase * K;

    const uint32_t sbase = smem_u32(smem);

    // cp.async: 4 threads per row, 2 chunks (32B) each; 64 rows per pass, 2 passes
    const int ldr = tid >> 2;            // row 0..63
    const int ldc = (tid & 3) * 2;       // chunk 0,2,4,6

    float acc[4][4][4];
    #pragma unroll
    for (int mf = 0; mf < 4; mf++)
        #pragma unroll
        for (int nf = 0; nf < 4; nf++)
            #pragma unroll
            for (int e = 0; e < 4; e++) acc[mf][nf][e] = 0.0f;

    const int nk = K >> 6;   // BK = 64 halves

    // ldmatrix per-lane address pieces
    const int arow = (lane & 7) + ((lane >> 3) & 1) * 8;
    const int kadd = (lane >> 4) * 8;

    // ---- prefetch STAGES-1 = 2 stages ----
    #pragma unroll
    for (int s = 0; s < STAGES - 1; s++) {
        uint32_t ad = sbase + s * STAGEB + ldr * ROWB + ldc * 16;
        const __half* ag = A  + (long)ldr * K + s * 64 + ldc * 8;
        const __half* bg = Bm + (long)ldr * K + s * 64 + ldc * 8;
        #pragma unroll
        for (int p = 0; p < 2; p++) {   // rows ldr, ldr+64
            CP16(ad + p * 64 * ROWB,          ag + (long)p * 64 * K);
            CP16(ad + p * 64 * ROWB + 16,     ag + (long)p * 64 * K + 8);
            CP16(ad + p * 64 * ROWB + TILEB,      bg + (long)p * 64 * K);
            CP16(ad + p * 64 * ROWB + TILEB + 16, bg + (long)p * 64 * K + 8);
        }
        CPCOMMIT();
    }

    for (int ck = 0; ck < nk; ck++) {
        CPWAIT1();
        __syncthreads();

        // issue next stage
        const int nxt = ck + STAGES - 1;
        if (nxt < nk) {
            const int nb = nxt % STAGES;
            uint32_t ad = sbase + nb * STAGEB + ldr * ROWB + ldc * 16;
            const __half* ag = A  + (long)ldr * K + nxt * 64 + ldc * 8;
            const __half* bg = Bm + (long)ldr * K + nxt * 64 + ldc * 8;
            #pragma unroll
            for (int p = 0; p < 2; p++) {
                CP16(ad + p * 64 * ROWB,          ag + (long)p * 64 * K);
                CP16(ad + p * 64 * ROWB + 16,     ag + (long)p * 64 * K + 8);
                CP16(ad + p * 64 * ROWB + TILEB,      bg + (long)p * 64 * K);
                CP16(ad + p * 64 * ROWB + TILEB + 16, bg + (long)p * 64 * K + 8);
            }
        }
        CPCOMMIT();

        // compute this stage: 4 k16-steps
        const int buf = ck % STAGES;
        const uint32_t abase = sbase + buf * STAGEB;
        const uint32_t bbase = abase + TILEB;
        #pragma unroll
        for (int ks = 0; ks < 4; ks++) {
            uint32_t a[4][4], b[4][2];
            #pragma unroll
            for (int mf = 0; mf < 4; mf++) {
                uint32_t addr = abase + (wm * 64 + mf * 16 + arow) * ROWB + (ks * 16 + kadd) * 2;
                LDSM4(a[mf][0], a[mf][1], a[mf][2], a[mf][3], addr);
            }
            #pragma unroll
            for (int p = 0; p < 2; p++) {
                uint32_t t0, t1, t2, t3;
                uint32_t addr = bbase + (wn * 32 + p * 16 + arow) * ROWB + (ks * 16 + kadd) * 2;
                LDSM4(t0, t1, t2, t3, addr);
                b[p * 2][0] = t0; b[p * 2][1] = t2;
                b[p * 2 + 1][0] = t1; b[p * 2 + 1][1] = t3;
            }
            #pragma unroll
            for (int mf = 0; mf < 4; mf++)
                #pragma unroll
                for (int nf = 0; nf < 4; nf++)
                    MMA16816(acc[mf][nf], a[mf], b[nf]);
        }
    }

    // ---- epilogue ----
    const int r0 = lane >> 2;
    const int c0 = (lane & 3) * 2;
    #pragma unroll
    for (int mf = 0; mf < 4; mf++) {
        #pragma unroll
        for (int nf = 0; nf < 4; nf++) {
            int gr = rowBase + wm * 64 + mf * 16 + r0;
            int gc = colBase + wn * 32 + nf * 8 + c0;
            float* ac = acc[mf][nf];
            if (MODE == 0) {
                float* C = (float*)Cv + (long)blockIdx.z * sC;
                *(float2*)(C + (long)gr * N + gc)       = make_float2(ac[0], ac[1]);
                *(float2*)(C + (long)(gr + 8) * N + gc) = make_float2(ac[2], ac[3]);
            } else {
                __half* C = (__half*)Cv + (long)blockIdx.z * sC;
                float b0 = __ldg(bias + gc), b1 = __ldg(bias + gc + 1);
                H2U u0, u1;
                u0.h = __floats2half2_rn(ac[0] + b0, ac[1] + b1);
                u1.h = __floats2half2_rn(ac[2] + b0, ac[3] + b1);
                *(unsigned*)(C + (long)gr * N + gc)       = u0.u;
                *(unsigned*)(C + (long)(gr + 8) * N + gc) = u1.u;
            }
        }
    }
}

// ---------------- f32 -> f16 convert, 3 tensors in one launch, 16 elem/thr ----
__global__ __launch_bounds__(256)
void f2h3_kernel(const float* __restrict__ in0, const float* __restrict__ in1,
                 const float* __restrict__ in2, __half* __restrict__ out)
{
    const float* in = (blockIdx.y == 0) ? in0 : (blockIdx.y == 1) ? in1 : in2;
    __half* o = out + (long)blockIdx.y * ((long)BB * SS * DD);
    long i = ((long)blockIdx.x * 256 + threadIdx.x) * 16;
    #pragma unroll
    for (int h = 0; h < 2; h++) {
        float4 a = *(const float4*)(in + i + h * 8);
        float4 b = *(const float4*)(in + i + h * 8 + 4);
        H2U h0, h1, h2, h3;
        h0.h = __floats2half2_rn(a.x, a.y); h1.h = __floats2half2_rn(a.z, a.w);
        h2.h = __floats2half2_rn(b.x, b.y); h3.h = __floats2half2_rn(b.z, b.w);
        *(uint4*)(o + i + h * 8) = make_uint4(h0.u, h1.u, h2.u, h3.u);
    }
}

// ---------------- transpose f32 [D][D] -> f16 [D][D]^T, 3 weights/launch ----
__global__ __launch_bounds__(256)
void transWh3_kernel(const float* __restrict__ w0, const float* __restrict__ w1,
                     const float* __restrict__ w2, __half* __restrict__ out)
{
    __shared__ float t[32][33];
    const float* in = (blockIdx.z == 0) ? w0 : (blockIdx.z == 1) ? w1 : w2;
    __half* o = out + (long)blockIdx.z * ((long)DD * DD);
    int tx = threadIdx.x, ty = threadIdx.y;
    int x = blockIdx.x * 32 + tx, y0 = blockIdx.y * 32 + ty;
    #pragma unroll
    for (int j = 0; j < 32; j += 8) t[ty + j][tx] = in[(long)(y0 + j) * DD + x];
    __syncthreads();
    int ox = blockIdx.y * 32 + tx, oy0 = blockIdx.x * 32 + ty;
    #pragma unroll
    for (int j = 0; j < 32; j += 8)
        o[(long)(oy0 + j) * DD + ox] = __float2half(t[tx][ty + j]);
}

// ---------------- transpose f16 [R][C] -> f16 [C][R], batched ----------------
__global__ __launch_bounds__(256)
void transH_kernel(const __half* __restrict__ in, __half* __restrict__ out,
                   int R, int C, long sIn, long sOut)
{
    __shared__ __half t[32][33];
    in  += (long)blockIdx.z * sIn;
    out += (long)blockIdx.z * sOut;
    int tx = threadIdx.x, ty = threadIdx.y;
    int x = blockIdx.x * 32 + tx, y0 = blockIdx.y * 32 + ty;
    #pragma unroll
    for (int j = 0; j < 32; j += 8) t[ty + j][tx] = in[(long)(y0 + j) * C + x];
    __syncthreads();
    int ox = blockIdx.y * 32 + tx, oy0 = blockIdx.x * 32 + ty;
    #pragma unroll
    for (int j = 0; j < 32; j += 8)
        out[(long)(oy0 + j) * R + ox] = t[tx][ty + j];
}

// ---------------- softmax(beta*x) f32 in -> f16 out ----------------
__global__ __launch_bounds__(256, 4)
void softmax_kernel(const float* __restrict__ s, __half* __restrict__ ah, float beta)
{
    const float* p = s + (long)blockIdx.x * SS;
    __half* po = ah + (long)blockIdx.x * SS;
    const int tid = threadIdx.x;

    float4 a = ((const float4*)p)[tid];
    float4 b = ((const float4*)p)[tid + 256];

    __shared__ float red[8];
    __shared__ float bc;

    float m = fmaxf(fmaxf(fmaxf(a.x, a.y), fmaxf(a.z, a.w)),
                    fmaxf(fmaxf(b.x, b.y), fmaxf(b.z, b.w)));
    #pragma unroll
    for (int o = 16; o; o >>= 1) m = fmaxf(m, __shfl_xor_sync(0xffffffffu, m, o));
    if ((tid & 31) == 0) red[tid >> 5] = m;
    __syncthreads();
    if (tid < 32) {
        float t = (tid < 8) ? red[tid] : -3.4e38f;
        #pragma unroll
        for (int o = 4; o; o >>= 1) t = fmaxf(t, __shfl_xor_sync(0xffffffffu, t, o));
        if (tid == 0) bc = t;
    }
    __syncthreads();
    m = bc;
    __syncthreads();

    a.x = __expf(beta * (a.x - m)); a.y = __expf(beta * (a.y - m));
    a.z = __expf(beta * (a.z - m)); a.w = __expf(beta * (a.w - m));
    b.x = __expf(beta * (b.x - m)); b.y = __expf(beta * (b.y - m));
    b.z = __expf(beta * (b.z - m)); b.w = __expf(beta * (b.w - m));
    float sum = (a.x + a.y) + (a.z + a.w) + (b.x + b.y) + (b.z + b.w);
    #pragma unroll
    for (int o = 16; o; o >>= 1) sum += __shfl_xor_sync(0xffffffffu, sum, o);
    if ((tid & 31) == 0) red[tid >> 5] = sum;
    __syncthreads();
    if (tid < 32) {
        float t = (tid < 8) ? red[tid] : 0.0f;
        #pragma unroll
        for (int o = 4; o; o >>= 1) t += __shfl_xor_sync(0xffffffffu, t, o);
        if (tid == 0) bc = t;
    }
    __syncthreads();
    float inv = 1.0f / bc;

    H2U u0, u1, u2, u3;
    u0.h = __floats2half2_rn(a.x * inv, a.y * inv);
    u1.h = __floats2half2_rn(a.z * inv, a.w * inv);
    u2.h = __floats2half2_rn(b.x * inv, b.y * inv);
    u3.h = __floats2half2_rn(b.z * inv, b.w * inv);
    ((uint2*)po)[tid]       = make_uint2(u0.u, u1.u);
    ((uint2*)po)[tid + 256] = make_uint2(u2.u, u3.u);
}

// ---------------------------------------------------------------------------
extern "C" void kernel_launch(void* const* d_in, const int* in_sizes, int n_in,
                              void* d_out, int out_size)
{
    const float* query = (const float*)d_in[0];
    const float* key   = (const float*)d_in[1];
    const float* value = (const float*)d_in[2];
    const float* Wq    = (const float*)d_in[3];
    const float* bq    = (const float*)d_in[4];
    const float* Wk    = (const float*)d_in[5];
    const float* bk    = (const float*)d_in[6];
    const float* Wv    = (const float*)d_in[7];
    const float* bv    = (const float*)d_in[8];
    float* out = (float*)d_out;

    __half *xh, *wT, *q, *k, *v, *vT, *ah;
    float *s;
    cudaGetSymbolAddress((void**)&xh, g_xh);
    cudaGetSymbolAddress((void**)&wT, g_wT);
    cudaGetSymbolAddress((void**)&q,  g_q);
    cudaGetSymbolAddress((void**)&k,  g_k);
    cudaGetSymbolAddress((void**)&v,  g_v);
    cudaGetSymbolAddress((void**)&vT, g_vT);
    cudaGetSymbolAddress((void**)&s,  g_s);
    cudaGetSymbolAddress((void**)&ah, g_a);

    static bool attr_set = false;
    if (!attr_set) {
        cudaFuncSetAttribute(gemm_h<0>, cudaFuncAttributeMaxDynamicSharedMemorySize, SMEMB);
        cudaFuncSetAttribute(gemm_h<1>, cudaFuncAttributeMaxDynamicSharedMemorySize, SMEMB);
        attr_set = true;
    }

    const long NX = (long)BB * SS * DD;   // 8M elems
    const long ND = (long)DD * DD;

    // 1) convert inputs to fp16 (one launch, 16 elem/thread)
    dim3 gF((unsigned)(NX / (256 * 16)), 3);
    f2h3_kernel<<<gF, 256>>>(query, key, value, xh);

    // 2) transpose + convert weights -> [n][k] fp16 (one launch)
    dim3 tT(32, 8);
    dim3 gW(DD / 32, DD / 32, 3);
    transWh3_kernel<<<gW, tT>>>(Wq, Wk, Wv, wT);

    // 3) projections: fp16 out + bias
    dim3 gProj(DD / 128, (BB * SS) / 128, 1);
    gemm_h<1><<<gProj, 256, SMEMB>>>(xh + 0 * NX, wT + 0 * ND, q, bq, BB * SS, DD, DD, 0, 0, 0);
    gemm_h<1><<<gProj, 256, SMEMB>>>(xh + 1 * NX, wT + 1 * ND, k, bk, BB * SS, DD, DD, 0, 0, 0);
    gemm_h<1><<<gProj, 256, SMEMB>>>(xh + 2 * NX, wT + 2 * ND, v, bv, BB * SS, DD, DD, 0, 0, 0);

    // 4) transpose v per batch -> vT [d][s]
    dim3 gVT(DD / 32, SS / 32, BB);
    transH_kernel<<<gVT, tT>>>(v, vT, SS, DD, (long)SS * DD, (long)SS * DD);

    // 5) scores: S = q k^T (f32 out)
    dim3 gScores(SS / 128, SS / 128, BB);
    gemm_h<0><<<gScores, 256, SMEMB>>>(q, k, s, nullptr, SS, SS, DD,
                                       (long)SS * DD, (long)SS * DD, (long)SS * SS);

    // 6) softmax(beta*S) -> fp16 A
    softmax_kernel<<<BB * SS, 256>>>(s, ah, BETA_F);

    // 7) out = A vT^T (f32 out to d_out)
    dim3 gOut(DD / 128, SS / 128, BB);
    gemm_h<0><<<gOut, 256, SMEMB>>>(ah, vT, out, nullptr, SS, DD, SS,
                                    (long)SS * SS, (long)SS * DD, (long)SS * DD);
}